// round 2
// baseline (speedup 1.0000x reference)
#include <cuda_runtime.h>

#define B_   512
#define M_   256
#define BM_  (B_*M_)      // 131072 rows
#define NGL  4
#define NRB  3

// Scratch (allocation-free rule: __device__ globals)
__device__ float g_Y[BM_*128];
__device__ float g_X[BM_*128];
__device__ float g_H[BM_*128];

// ---------------------------------------------------------------------------
// Y[r,n] = op( sum_k X[r,k]*W[n,k] (+bias[n]) ) (+ res[r,n])
// R multiple of 128, K=128, N=128. 128x128 tile per block, 256 threads,
// 8x8 accumulators per thread.
// ---------------------------------------------------------------------------
template<bool HAS_BIAS, bool RELU, bool RES>
__global__ __launch_bounds__(256)
void gemm128(const float* __restrict__ X, const float* __restrict__ W,
             const float* __restrict__ bias, const float* __restrict__ res,
             float* __restrict__ Y)
{
    __shared__ float Xs[128][33];
    __shared__ float Ws[128][33];
    const int tid = threadIdx.x;
    const int tx = tid & 15, ty = tid >> 4;
    const long row0 = (long)blockIdx.x * 128;

    float acc[8][8];
#pragma unroll
    for (int i = 0; i < 8; i++)
#pragma unroll
        for (int j = 0; j < 8; j++) acc[i][j] = 0.f;

    for (int kc = 0; kc < 128; kc += 32) {
#pragma unroll
        for (int it = 0; it < 16; it++) {
            int idx = tid + it * 256;
            int r = idx >> 5, k = idx & 31;
            Xs[r][k] = X[(row0 + r) * 128 + kc + k];
            Ws[r][k] = W[r * 128 + kc + k];
        }
        __syncthreads();
#pragma unroll 8
        for (int k = 0; k < 32; k++) {
            float a[8], w[8];
#pragma unroll
            for (int i = 0; i < 8; i++) a[i] = Xs[ty + 16 * i][k];
#pragma unroll
            for (int j = 0; j < 8; j++) w[j] = Ws[tx + 16 * j][k];
#pragma unroll
            for (int i = 0; i < 8; i++)
#pragma unroll
                for (int j = 0; j < 8; j++)
                    acc[i][j] = fmaf(a[i], w[j], acc[i][j]);
        }
        __syncthreads();
    }

#pragma unroll
    for (int j = 0; j < 8; j++) {
        int col = tx + 16 * j;
        float bv = HAS_BIAS ? bias[col] : 0.f;
#pragma unroll
        for (int i = 0; i < 8; i++) {
            long row = row0 + ty + 16 * i;
            float v = acc[i][j] + bv;
            if (RELU) v = fmaxf(v, 0.f);
            if (RES)  v += res[row * 128 + col];
            Y[row * 128 + col] = v;
        }
    }
}

// ---------------------------------------------------------------------------
// Xout[b,m,p] = relu( sum_n G0[b,m,n] * Yin[b,n,p] ),  M=256, N(p)=128, K(n)=256
// grid (2, 512): 128-row tile x full 128 cols per block.
// ---------------------------------------------------------------------------
__global__ __launch_bounds__(256)
void bmm_relu(const float* __restrict__ G, const float* __restrict__ Yin,
              float* __restrict__ Xout)
{
    __shared__ float As[128][33];
    __shared__ float Bs[32][129];
    const int tid = threadIdx.x;
    const int tx = tid & 15, ty = tid >> 4;
    const int b = blockIdx.y;
    const int row0 = blockIdx.x * 128;
    const float* A  = G   + (long)b * M_ * M_;
    const float* Bm = Yin + (long)b * M_ * 128;

    float acc[8][8];
#pragma unroll
    for (int i = 0; i < 8; i++)
#pragma unroll
        for (int j = 0; j < 8; j++) acc[i][j] = 0.f;

    for (int kc = 0; kc < 256; kc += 32) {
#pragma unroll
        for (int it = 0; it < 16; it++) {
            int idx = tid + it * 256;
            int r = idx >> 5, k = idx & 31;
            As[r][k] = A[(row0 + r) * 256 + kc + k];
        }
#pragma unroll
        for (int it = 0; it < 16; it++) {
            int idx = tid + it * 256;
            int k = idx >> 7, n = idx & 127;
            Bs[k][n] = Bm[(kc + k) * 128 + n];
        }
        __syncthreads();
#pragma unroll 8
        for (int k = 0; k < 32; k++) {
            float a[8], w[8];
#pragma unroll
            for (int i = 0; i < 8; i++) a[i] = As[ty + 16 * i][k];
#pragma unroll
            for (int j = 0; j < 8; j++) w[j] = Bs[k][tx + 16 * j];
#pragma unroll
            for (int i = 0; i < 8; i++)
#pragma unroll
                for (int j = 0; j < 8; j++)
                    acc[i][j] = fmaf(a[i], w[j], acc[i][j]);
        }
        __syncthreads();
    }

    float* O = Xout + (long)b * M_ * 128;
#pragma unroll
    for (int j = 0; j < 8; j++) {
        int col = tx + 16 * j;
#pragma unroll
        for (int i = 0; i < 8; i++) {
            int row = row0 + ty + 16 * i;
            O[row * 128 + col] = fmaxf(acc[i][j], 0.f);
        }
    }
}

// ---------------------------------------------------------------------------
// Fused final: out[r] = f2_b + sum_{n<1024} f2_W[n] * relu( H[r,:]·f1_W[n,:] + f1_b[n] )
// 128-row tile per block; loop n in chunks of 128, k in chunks of 32.
// ---------------------------------------------------------------------------
__global__ __launch_bounds__(256)
void f1f2_fused(const float* __restrict__ H, const float* __restrict__ W1,
                const float* __restrict__ b1, const float* __restrict__ W2,
                const float* __restrict__ b2, float* __restrict__ out)
{
    __shared__ float Xs[128][33];
    __shared__ float Ws[128][33];
    __shared__ float red[128][17];
    const int tid = threadIdx.x;
    const int tx = tid & 15, ty = tid >> 4;
    const long row0 = (long)blockIdx.x * 128;

    float psum[8];
#pragma unroll
    for (int i = 0; i < 8; i++) psum[i] = 0.f;

    for (int nc = 0; nc < 1024; nc += 128) {
        float acc[8][8];
#pragma unroll
        for (int i = 0; i < 8; i++)
#pragma unroll
            for (int j = 0; j < 8; j++) acc[i][j] = 0.f;

        for (int kc = 0; kc < 128; kc += 32) {
#pragma unroll
            for (int it = 0; it < 16; it++) {
                int idx = tid + it * 256;
                int r = idx >> 5, k = idx & 31;
                Xs[r][k] = H[(row0 + r) * 128 + kc + k];
                Ws[r][k] = W1[(long)(nc + r) * 128 + kc + k];
            }
            __syncthreads();
#pragma unroll 8
            for (int k = 0; k < 32; k++) {
                float a[8], w[8];
#pragma unroll
                for (int i = 0; i < 8; i++) a[i] = Xs[ty + 16 * i][k];
#pragma unroll
                for (int j = 0; j < 8; j++) w[j] = Ws[tx + 16 * j][k];
#pragma unroll
                for (int i = 0; i < 8; i++)
#pragma unroll
                    for (int j = 0; j < 8; j++)
                        acc[i][j] = fmaf(a[i], w[j], acc[i][j]);
            }
            __syncthreads();
        }

#pragma unroll
        for (int j = 0; j < 8; j++) {
            int col = nc + tx + 16 * j;
            float bb = b1[col];
            float sc = W2[col];
#pragma unroll
            for (int i = 0; i < 8; i++)
                psum[i] = fmaf(fmaxf(acc[i][j] + bb, 0.f), sc, psum[i]);
        }
    }

#pragma unroll
    for (int i = 0; i < 8; i++) red[ty + 16 * i][tx] = psum[i];
    __syncthreads();
    if (tid < 128) {
        float s = b2[0];
#pragma unroll
        for (int t = 0; t < 16; t++) s += red[tid][t];
        out[row0 + tid] = s;
    }
}

// ---------------------------------------------------------------------------
extern "C" void kernel_launch(void* const* d_in, const int* in_sizes, int n_in,
                              void* d_out, int out_size)
{
    const float* G     = (const float*)d_in[0];
    const float* xG    = (const float*)d_in[1];
    const float* gmlW  = (const float*)d_in[2];
    const float* gmlB  = (const float*)d_in[3];
    const float* lin0W = (const float*)d_in[4];
    const float* lin0B = (const float*)d_in[5];
    const float* rinW  = (const float*)d_in[6];
    const float* rinB  = (const float*)d_in[7];
    const float* rb1W  = (const float*)d_in[8];
    const float* rb1B  = (const float*)d_in[9];
    const float* rb2W  = (const float*)d_in[10];
    const float* routW = (const float*)d_in[11];
    const float* routB = (const float*)d_in[12];
    const float* f1W   = (const float*)d_in[13];
    const float* f1B   = (const float*)d_in[14];
    const float* f2W   = (const float*)d_in[15];
    const float* f2B   = (const float*)d_in[16];
    float* out = (float*)d_out;

    float *bY, *bX, *bH;
    cudaGetSymbolAddress((void**)&bY, g_Y);
    cudaGetSymbolAddress((void**)&bX, g_X);
    cudaGetSymbolAddress((void**)&bH, g_H);

    const int GB = BM_ / 128;   // 1024 blocks
    dim3 blk(256);

    // GNN message-passing layers
    const float* xcur = xG;
    for (int l = 0; l < NGL; l++) {
        gemm128<true, false, false><<<GB, blk>>>(xcur, gmlW + (long)l * 128 * 128,
                                                 gmlB + l * 128, nullptr, bY);
        bmm_relu<<<dim3(2, B_), blk>>>(G, bY, bX);
        xcur = bX;
    }

    // MLP trunk
    gemm128<true, false, false><<<GB, blk>>>(bX, lin0W, lin0B, nullptr, bH);
    gemm128<true, false, false><<<GB, blk>>>(bH, rinW, rinB, nullptr, bX);
    for (int i = 0; i < NRB; i++) {
        gemm128<true, true,  false><<<GB, blk>>>(bX, rb1W + (long)i * 128 * 128,
                                                 rb1B + i * 128, nullptr, bY);
        gemm128<false, false, true><<<GB, blk>>>(bY, rb2W + (long)i * 128 * 128,
                                                 nullptr, bX, bX);
    }
    gemm128<true, false, false><<<GB, blk>>>(bX, routW, routB, nullptr, bH);

    // Fused f1 (relu) + f2 head
    f1f2_fused<<<GB, blk>>>(bH, f1W, f1B, f2W, f2B, out);
}

// round 3
// speedup vs baseline: 1.0058x; 1.0058x over previous
#include <cuda_runtime.h>

#define B_   512
#define M_   256
#define BM_  (B_*M_)      // 131072 rows
#define NGL  4
#define NRB  3

// Scratch (allocation-free rule: __device__ globals)
__device__ float g_Y[BM_*128];
__device__ float g_X[BM_*128];
__device__ float g_H[BM_*128];

// ---------------------------------------------------------------------------
// Y[r,n] = op( sum_k X[r,k]*W[n,k] (+bias[n]) ) (+ res[r,n])
// R multiple of 128, K=128, N=128. 128x128 tile per block, 256 threads,
// 8x8 accumulators per thread.
// ---------------------------------------------------------------------------
template<bool HAS_BIAS, bool RELU, bool RES>
__global__ __launch_bounds__(256)
void gemm128(const float* __restrict__ X, const float* __restrict__ W,
             const float* __restrict__ bias, const float* __restrict__ res,
             float* __restrict__ Y)
{
    __shared__ float Xs[128][33];
    __shared__ float Ws[128][33];
    const int tid = threadIdx.x;
    const int tx = tid & 15, ty = tid >> 4;
    const long row0 = (long)blockIdx.x * 128;

    float acc[8][8];
#pragma unroll
    for (int i = 0; i < 8; i++)
#pragma unroll
        for (int j = 0; j < 8; j++) acc[i][j] = 0.f;

    for (int kc = 0; kc < 128; kc += 32) {
#pragma unroll
        for (int it = 0; it < 16; it++) {
            int idx = tid + it * 256;
            int r = idx >> 5, k = idx & 31;
            Xs[r][k] = X[(row0 + r) * 128 + kc + k];
            Ws[r][k] = W[r * 128 + kc + k];
        }
        __syncthreads();
#pragma unroll 8
        for (int k = 0; k < 32; k++) {
            float a[8], w[8];
#pragma unroll
            for (int i = 0; i < 8; i++) a[i] = Xs[ty + 16 * i][k];
#pragma unroll
            for (int j = 0; j < 8; j++) w[j] = Ws[tx + 16 * j][k];
#pragma unroll
            for (int i = 0; i < 8; i++)
#pragma unroll
                for (int j = 0; j < 8; j++)
                    acc[i][j] = fmaf(a[i], w[j], acc[i][j]);
        }
        __syncthreads();
    }

#pragma unroll
    for (int j = 0; j < 8; j++) {
        int col = tx + 16 * j;
        float bv = HAS_BIAS ? bias[col] : 0.f;
#pragma unroll
        for (int i = 0; i < 8; i++) {
            long row = row0 + ty + 16 * i;
            float v = acc[i][j] + bv;
            if (RELU) v = fmaxf(v, 0.f);
            if (RES)  v += res[row * 128 + col];
            Y[row * 128 + col] = v;
        }
    }
}

// ---------------------------------------------------------------------------
// Xout[b,m,p] = relu( sum_n G0[b,m,n] * Yin[b,n,p] ),  M=256, N(p)=128, K(n)=256
// grid (2, 512): 128-row tile x full 128 cols per block.
// ---------------------------------------------------------------------------
__global__ __launch_bounds__(256)
void bmm_relu(const float* __restrict__ G, const float* __restrict__ Yin,
              float* __restrict__ Xout)
{
    __shared__ float As[128][33];
    __shared__ float Bs[32][129];
    const int tid = threadIdx.x;
    const int tx = tid & 15, ty = tid >> 4;
    const int b = blockIdx.y;
    const int row0 = blockIdx.x * 128;
    const float* A  = G   + (long)b * M_ * M_;
    const float* Bm = Yin + (long)b * M_ * 128;

    float acc[8][8];
#pragma unroll
    for (int i = 0; i < 8; i++)
#pragma unroll
        for (int j = 0; j < 8; j++) acc[i][j] = 0.f;

    for (int kc = 0; kc < 256; kc += 32) {
#pragma unroll
        for (int it = 0; it < 16; it++) {
            int idx = tid + it * 256;
            int r = idx >> 5, k = idx & 31;
            As[r][k] = A[(row0 + r) * 256 + kc + k];
        }
#pragma unroll
        for (int it = 0; it < 16; it++) {
            int idx = tid + it * 256;
            int k = idx >> 7, n = idx & 127;
            Bs[k][n] = Bm[(kc + k) * 128 + n];
        }
        __syncthreads();
#pragma unroll 8
        for (int k = 0; k < 32; k++) {
            float a[8], w[8];
#pragma unroll
            for (int i = 0; i < 8; i++) a[i] = As[ty + 16 * i][k];
#pragma unroll
            for (int j = 0; j < 8; j++) w[j] = Bs[k][tx + 16 * j];
#pragma unroll
            for (int i = 0; i < 8; i++)
#pragma unroll
                for (int j = 0; j < 8; j++)
                    acc[i][j] = fmaf(a[i], w[j], acc[i][j]);
        }
        __syncthreads();
    }

    float* O = Xout + (long)b * M_ * 128;
#pragma unroll
    for (int j = 0; j < 8; j++) {
        int col = tx + 16 * j;
#pragma unroll
        for (int i = 0; i < 8; i++) {
            int row = row0 + ty + 16 * i;
            O[row * 128 + col] = fmaxf(acc[i][j], 0.f);
        }
    }
}

// ---------------------------------------------------------------------------
// Fused final: out[r] = f2_b + sum_{n<1024} f2_W[n] * relu( H[r,:]·f1_W[n,:] + f1_b[n] )
// 128-row tile per block; loop n in chunks of 128, k in chunks of 32.
// ---------------------------------------------------------------------------
__global__ __launch_bounds__(256)
void f1f2_fused(const float* __restrict__ H, const float* __restrict__ W1,
                const float* __restrict__ b1, const float* __restrict__ W2,
                const float* __restrict__ b2, float* __restrict__ out)
{
    __shared__ float Xs[128][33];
    __shared__ float Ws[128][33];
    __shared__ float red[128][17];
    const int tid = threadIdx.x;
    const int tx = tid & 15, ty = tid >> 4;
    const long row0 = (long)blockIdx.x * 128;

    float psum[8];
#pragma unroll
    for (int i = 0; i < 8; i++) psum[i] = 0.f;

    for (int nc = 0; nc < 1024; nc += 128) {
        float acc[8][8];
#pragma unroll
        for (int i = 0; i < 8; i++)
#pragma unroll
            for (int j = 0; j < 8; j++) acc[i][j] = 0.f;

        for (int kc = 0; kc < 128; kc += 32) {
#pragma unroll
            for (int it = 0; it < 16; it++) {
                int idx = tid + it * 256;
                int r = idx >> 5, k = idx & 31;
                Xs[r][k] = H[(row0 + r) * 128 + kc + k];
                Ws[r][k] = W1[(long)(nc + r) * 128 + kc + k];
            }
            __syncthreads();
#pragma unroll 8
            for (int k = 0; k < 32; k++) {
                float a[8], w[8];
#pragma unroll
                for (int i = 0; i < 8; i++) a[i] = Xs[ty + 16 * i][k];
#pragma unroll
                for (int j = 0; j < 8; j++) w[j] = Ws[tx + 16 * j][k];
#pragma unroll
                for (int i = 0; i < 8; i++)
#pragma unroll
                    for (int j = 0; j < 8; j++)
                        acc[i][j] = fmaf(a[i], w[j], acc[i][j]);
            }
            __syncthreads();
        }

#pragma unroll
        for (int j = 0; j < 8; j++) {
            int col = nc + tx + 16 * j;
            float bb = b1[col];
            float sc = W2[col];
#pragma unroll
            for (int i = 0; i < 8; i++)
                psum[i] = fmaf(fmaxf(acc[i][j] + bb, 0.f), sc, psum[i]);
        }
    }

#pragma unroll
    for (int i = 0; i < 8; i++) red[ty + 16 * i][tx] = psum[i];
    __syncthreads();
    if (tid < 128) {
        float s = b2[0];
#pragma unroll
        for (int t = 0; t < 16; t++) s += red[tid][t];
        out[row0 + tid] = s;
    }
}

// ---------------------------------------------------------------------------
extern "C" void kernel_launch(void* const* d_in, const int* in_sizes, int n_in,
                              void* d_out, int out_size)
{
    const float* G     = (const float*)d_in[0];
    const float* xG    = (const float*)d_in[1];
    const float* gmlW  = (const float*)d_in[2];
    const float* gmlB  = (const float*)d_in[3];
    const float* lin0W = (const float*)d_in[4];
    const float* lin0B = (const float*)d_in[5];
    const float* rinW  = (const float*)d_in[6];
    const float* rinB  = (const float*)d_in[7];
    const float* rb1W  = (const float*)d_in[8];
    const float* rb1B  = (const float*)d_in[9];
    const float* rb2W  = (const float*)d_in[10];
    const float* routW = (const float*)d_in[11];
    const float* routB = (const float*)d_in[12];
    const float* f1W   = (const float*)d_in[13];
    const float* f1B   = (const float*)d_in[14];
    const float* f2W   = (const float*)d_in[15];
    const float* f2B   = (const float*)d_in[16];
    float* out = (float*)d_out;

    float *bY, *bX, *bH;
    cudaGetSymbolAddress((void**)&bY, g_Y);
    cudaGetSymbolAddress((void**)&bX, g_X);
    cudaGetSymbolAddress((void**)&bH, g_H);

    const int GB = BM_ / 128;   // 1024 blocks
    dim3 blk(256);

    // GNN message-passing layers
    const float* xcur = xG;
    for (int l = 0; l < NGL; l++) {
        gemm128<true, false, false><<<GB, blk>>>(xcur, gmlW + (long)l * 128 * 128,
                                                 gmlB + l * 128, nullptr, bY);
        bmm_relu<<<dim3(2, B_), blk>>>(G, bY, bX);
        xcur = bX;
    }

    // MLP trunk
    gemm128<true, false, false><<<GB, blk>>>(bX, lin0W, lin0B, nullptr, bH);
    gemm128<true, false, false><<<GB, blk>>>(bH, rinW, rinB, nullptr, bX);
    for (int i = 0; i < NRB; i++) {
        gemm128<true, true,  false><<<GB, blk>>>(bX, rb1W + (long)i * 128 * 128,
                                                 rb1B + i * 128, nullptr, bY);
        gemm128<false, false, true><<<GB, blk>>>(bY, rb2W + (long)i * 128 * 128,
                                                 nullptr, bX, bX);
    }
    gemm128<true, false, false><<<GB, blk>>>(bX, routW, routB, nullptr, bH);

    // Fused f1 (relu) + f2 head
    f1f2_fused<<<GB, blk>>>(bH, f1W, f1B, f2W, f2B, out);
}

// round 4
// speedup vs baseline: 1.0062x; 1.0004x over previous
#include <cuda_runtime.h>

#define B_   512
#define M_   256
#define BM_  (B_*M_)      // 131072 rows
#define NGL  4
#define NRB  3

// Scratch (allocation-free rule: __device__ globals)
__device__ float g_Y[BM_*128];
__device__ float g_X[BM_*128];
__device__ float g_H[BM_*128];

// ---------------------------------------------------------------------------
// Y[r,n] = op( sum_k X[r,k]*W[n,k] (+bias[n]) ) (+ res[r,n])
// R multiple of 128, K=128, N=128. 128x128 tile per block, 256 threads,
// 8x8 accumulators per thread.
// ---------------------------------------------------------------------------
template<bool HAS_BIAS, bool RELU, bool RES>
__global__ __launch_bounds__(256)
void gemm128(const float* __restrict__ X, const float* __restrict__ W,
             const float* __restrict__ bias, const float* __restrict__ res,
             float* __restrict__ Y)
{
    __shared__ float Xs[128][33];
    __shared__ float Ws[128][33];
    const int tid = threadIdx.x;
    const int tx = tid & 15, ty = tid >> 4;
    const long row0 = (long)blockIdx.x * 128;

    float acc[8][8];
#pragma unroll
    for (int i = 0; i < 8; i++)
#pragma unroll
        for (int j = 0; j < 8; j++) acc[i][j] = 0.f;

    for (int kc = 0; kc < 128; kc += 32) {
#pragma unroll
        for (int it = 0; it < 16; it++) {
            int idx = tid + it * 256;
            int r = idx >> 5, k = idx & 31;
            Xs[r][k] = X[(row0 + r) * 128 + kc + k];
            Ws[r][k] = W[r * 128 + kc + k];
        }
        __syncthreads();
#pragma unroll 8
        for (int k = 0; k < 32; k++) {
            float a[8], w[8];
#pragma unroll
            for (int i = 0; i < 8; i++) a[i] = Xs[ty + 16 * i][k];
#pragma unroll
            for (int j = 0; j < 8; j++) w[j] = Ws[tx + 16 * j][k];
#pragma unroll
            for (int i = 0; i < 8; i++)
#pragma unroll
                for (int j = 0; j < 8; j++)
                    acc[i][j] = fmaf(a[i], w[j], acc[i][j]);
        }
        __syncthreads();
    }

#pragma unroll
    for (int j = 0; j < 8; j++) {
        int col = tx + 16 * j;
        float bv = HAS_BIAS ? bias[col] : 0.f;
#pragma unroll
        for (int i = 0; i < 8; i++) {
            long row = row0 + ty + 16 * i;
            float v = acc[i][j] + bv;
            if (RELU) v = fmaxf(v, 0.f);
            if (RES)  v += res[row * 128 + col];
            Y[row * 128 + col] = v;
        }
    }
}

// ---------------------------------------------------------------------------
// Xout[b,m,p] = relu( sum_n G0[b,m,n] * Yin[b,n,p] ),  M=256, N(p)=128, K(n)=256
// grid (2, 512): 128-row tile x full 128 cols per block.
// ---------------------------------------------------------------------------
__global__ __launch_bounds__(256)
void bmm_relu(const float* __restrict__ G, const float* __restrict__ Yin,
              float* __restrict__ Xout)
{
    __shared__ float As[128][33];
    __shared__ float Bs[32][129];
    const int tid = threadIdx.x;
    const int tx = tid & 15, ty = tid >> 4;
    const int b = blockIdx.y;
    const int row0 = blockIdx.x * 128;
    const float* A  = G   + (long)b * M_ * M_;
    const float* Bm = Yin + (long)b * M_ * 128;

    float acc[8][8];
#pragma unroll
    for (int i = 0; i < 8; i++)
#pragma unroll
        for (int j = 0; j < 8; j++) acc[i][j] = 0.f;

    for (int kc = 0; kc < 256; kc += 32) {
#pragma unroll
        for (int it = 0; it < 16; it++) {
            int idx = tid + it * 256;
            int r = idx >> 5, k = idx & 31;
            As[r][k] = A[(row0 + r) * 256 + kc + k];
        }
#pragma unroll
        for (int it = 0; it < 16; it++) {
            int idx = tid + it * 256;
            int k = idx >> 7, n = idx & 127;
            Bs[k][n] = Bm[(kc + k) * 128 + n];
        }
        __syncthreads();
#pragma unroll 8
        for (int k = 0; k < 32; k++) {
            float a[8], w[8];
#pragma unroll
            for (int i = 0; i < 8; i++) a[i] = As[ty + 16 * i][k];
#pragma unroll
            for (int j = 0; j < 8; j++) w[j] = Bs[k][tx + 16 * j];
#pragma unroll
            for (int i = 0; i < 8; i++)
#pragma unroll
                for (int j = 0; j < 8; j++)
                    acc[i][j] = fmaf(a[i], w[j], acc[i][j]);
        }
        __syncthreads();
    }

    float* O = Xout + (long)b * M_ * 128;
#pragma unroll
    for (int j = 0; j < 8; j++) {
        int col = tx + 16 * j;
#pragma unroll
        for (int i = 0; i < 8; i++) {
            int row = row0 + ty + 16 * i;
            O[row * 128 + col] = fmaxf(acc[i][j], 0.f);
        }
    }
}

// ---------------------------------------------------------------------------
// Fused final: out[r] = f2_b + sum_{n<1024} f2_W[n] * relu( H[r,:]·f1_W[n,:] + f1_b[n] )
// 128-row tile per block; loop n in chunks of 128, k in chunks of 32.
// ---------------------------------------------------------------------------
__global__ __launch_bounds__(256)
void f1f2_fused(const float* __restrict__ H, const float* __restrict__ W1,
                const float* __restrict__ b1, const float* __restrict__ W2,
                const float* __restrict__ b2, float* __restrict__ out)
{
    __shared__ float Xs[128][33];
    __shared__ float Ws[128][33];
    __shared__ float red[128][17];
    const int tid = threadIdx.x;
    const int tx = tid & 15, ty = tid >> 4;
    const long row0 = (long)blockIdx.x * 128;

    float psum[8];
#pragma unroll
    for (int i = 0; i < 8; i++) psum[i] = 0.f;

    for (int nc = 0; nc < 1024; nc += 128) {
        float acc[8][8];
#pragma unroll
        for (int i = 0; i < 8; i++)
#pragma unroll
            for (int j = 0; j < 8; j++) acc[i][j] = 0.f;

        for (int kc = 0; kc < 128; kc += 32) {
#pragma unroll
            for (int it = 0; it < 16; it++) {
                int idx = tid + it * 256;
                int r = idx >> 5, k = idx & 31;
                Xs[r][k] = H[(row0 + r) * 128 + kc + k];
                Ws[r][k] = W1[(long)(nc + r) * 128 + kc + k];
            }
            __syncthreads();
#pragma unroll 8
            for (int k = 0; k < 32; k++) {
                float a[8], w[8];
#pragma unroll
                for (int i = 0; i < 8; i++) a[i] = Xs[ty + 16 * i][k];
#pragma unroll
                for (int j = 0; j < 8; j++) w[j] = Ws[tx + 16 * j][k];
#pragma unroll
                for (int i = 0; i < 8; i++)
#pragma unroll
                    for (int j = 0; j < 8; j++)
                        acc[i][j] = fmaf(a[i], w[j], acc[i][j]);
            }
            __syncthreads();
        }

#pragma unroll
        for (int j = 0; j < 8; j++) {
            int col = nc + tx + 16 * j;
            float bb = b1[col];
            float sc = W2[col];
#pragma unroll
            for (int i = 0; i < 8; i++)
                psum[i] = fmaf(fmaxf(acc[i][j] + bb, 0.f), sc, psum[i]);
        }
    }

#pragma unroll
    for (int i = 0; i < 8; i++) red[ty + 16 * i][tx] = psum[i];
    __syncthreads();
    if (tid < 128) {
        float s = b2[0];
#pragma unroll
        for (int t = 0; t < 16; t++) s += red[tid][t];
        out[row0 + tid] = s;
    }
}

// ---------------------------------------------------------------------------
extern "C" void kernel_launch(void* const* d_in, const int* in_sizes, int n_in,
                              void* d_out, int out_size)
{
    const float* G     = (const float*)d_in[0];
    const float* xG    = (const float*)d_in[1];
    const float* gmlW  = (const float*)d_in[2];
    const float* gmlB  = (const float*)d_in[3];
    const float* lin0W = (const float*)d_in[4];
    const float* lin0B = (const float*)d_in[5];
    const float* rinW  = (const float*)d_in[6];
    const float* rinB  = (const float*)d_in[7];
    const float* rb1W  = (const float*)d_in[8];
    const float* rb1B  = (const float*)d_in[9];
    const float* rb2W  = (const float*)d_in[10];
    const float* routW = (const float*)d_in[11];
    const float* routB = (const float*)d_in[12];
    const float* f1W   = (const float*)d_in[13];
    const float* f1B   = (const float*)d_in[14];
    const float* f2W   = (const float*)d_in[15];
    const float* f2B   = (const float*)d_in[16];
    float* out = (float*)d_out;

    float *bY, *bX, *bH;
    cudaGetSymbolAddress((void**)&bY, g_Y);
    cudaGetSymbolAddress((void**)&bX, g_X);
    cudaGetSymbolAddress((void**)&bH, g_H);

    const int GB = BM_ / 128;   // 1024 blocks
    dim3 blk(256);

    // GNN message-passing layers
    const float* xcur = xG;
    for (int l = 0; l < NGL; l++) {
        gemm128<true, false, false><<<GB, blk>>>(xcur, gmlW + (long)l * 128 * 128,
                                                 gmlB + l * 128, nullptr, bY);
        bmm_relu<<<dim3(2, B_), blk>>>(G, bY, bX);
        xcur = bX;
    }

    // MLP trunk
    gemm128<true, false, false><<<GB, blk>>>(bX, lin0W, lin0B, nullptr, bH);
    gemm128<true, false, false><<<GB, blk>>>(bH, rinW, rinB, nullptr, bX);
    for (int i = 0; i < NRB; i++) {
        gemm128<true, true,  false><<<GB, blk>>>(bX, rb1W + (long)i * 128 * 128,
                                                 rb1B + i * 128, nullptr, bY);
        gemm128<false, false, true><<<GB, blk>>>(bY, rb2W + (long)i * 128 * 128,
                                                 nullptr, bX, bX);
    }
    gemm128<true, false, false><<<GB, blk>>>(bX, routW, routB, nullptr, bH);

    // Fused f1 (relu) + f2 head
    f1f2_fused<<<GB, blk>>>(bH, f1W, f1B, f2W, f2B, out);
}

// round 5
// speedup vs baseline: 2.3777x; 2.3631x over previous
#include <cuda_runtime.h>
#include <cstdint>

#define B_   512
#define M_   256
#define BM_  (B_*M_)      // 131072 rows
#define NGL  4
#define NRB  3

// Scratch (allocation-free rule: __device__ globals)
__device__ float g_Y[BM_*128];
__device__ float g_X[BM_*128];
__device__ float g_H[BM_*128];

// ---------------------------------------------------------------------------
// tf32 helpers
// ---------------------------------------------------------------------------
__device__ __forceinline__ uint32_t f2tf(float x) {
    uint32_t r;
    asm("cvt.rna.tf32.f32 %0, %1;" : "=r"(r) : "f"(x));
    return r;
}

__device__ __forceinline__ void mma8(float& c0, float& c1, float& c2, float& c3,
                                     uint32_t a0, uint32_t a1, uint32_t a2, uint32_t a3,
                                     uint32_t b0, uint32_t b1)
{
    asm volatile(
        "mma.sync.aligned.m16n8k8.row.col.f32.tf32.tf32.f32 "
        "{%0,%1,%2,%3}, {%4,%5,%6,%7}, {%8,%9}, {%0,%1,%2,%3};"
        : "+f"(c0), "+f"(c1), "+f"(c2), "+f"(c3)
        : "r"(a0), "r"(a1), "r"(a2), "r"(a3), "r"(b0), "r"(b1));
}

// Shared-tile pad: 36 => bank = (4*g + t) % 32, all 32 lanes distinct for both
// A-frag (row-stride) and B-frag (row-stride) reads.
#define PAD 36

// ---------------------------------------------------------------------------
// Y[r,n] = op( sum_k X[r,k]*W[n,k] (+bias[n]) ) (+ res[r,n])
// 128x128 tile, K=128 in 4 chunks of 32. 256 threads = 8 warps (2 M x 4 N),
// warp tile 64x32 = 4 m16 atoms x 4 n8 atoms. tf32 tensor cores.
// ---------------------------------------------------------------------------
template<bool HAS_BIAS, bool RELU, bool RES>
__global__ __launch_bounds__(256)
void gemm128_tc(const float* __restrict__ X, const float* __restrict__ W,
                const float* __restrict__ bias, const float* __restrict__ res,
                float* __restrict__ Y)
{
    __shared__ uint32_t As[128][PAD];
    __shared__ uint32_t Bs[128][PAD];

    const int tid  = threadIdx.x;
    const int lane = tid & 31, wid = tid >> 5;
    const int g = lane >> 2, t = lane & 3;
    const int m0 = (wid >> 2) * 64;
    const int n0 = (wid & 3) * 32;
    const long row0 = (long)blockIdx.x * 128;

    float acc[4][4][4];
#pragma unroll
    for (int i = 0; i < 4; i++)
#pragma unroll
        for (int j = 0; j < 4; j++)
#pragma unroll
            for (int q = 0; q < 4; q++) acc[i][j][q] = 0.f;

    for (int kc = 0; kc < 128; kc += 32) {
#pragma unroll
        for (int it = 0; it < 4; it++) {
            int v = tid + it * 256;          // 0..1023 float4 slots
            int r = v >> 3, c = (v & 7) * 4;
            float4 x4 = *(const float4*)&X[(row0 + r) * 128 + kc + c];
            As[r][c+0] = f2tf(x4.x); As[r][c+1] = f2tf(x4.y);
            As[r][c+2] = f2tf(x4.z); As[r][c+3] = f2tf(x4.w);
            float4 w4 = *(const float4*)&W[r * 128 + kc + c];
            Bs[r][c+0] = f2tf(w4.x); Bs[r][c+1] = f2tf(w4.y);
            Bs[r][c+2] = f2tf(w4.z); Bs[r][c+3] = f2tf(w4.w);
        }
        __syncthreads();

#pragma unroll
        for (int ks = 0; ks < 4; ks++) {
            const int k0 = ks * 8;
            uint32_t af[4][4];
#pragma unroll
            for (int i = 0; i < 4; i++) {
                int mr = m0 + 16 * i;
                af[i][0] = As[mr + g    ][k0 + t];
                af[i][1] = As[mr + g + 8][k0 + t];
                af[i][2] = As[mr + g    ][k0 + t + 4];
                af[i][3] = As[mr + g + 8][k0 + t + 4];
            }
            uint32_t bf[4][2];
#pragma unroll
            for (int j = 0; j < 4; j++) {
                int nb = n0 + 8 * j + g;
                bf[j][0] = Bs[nb][k0 + t];
                bf[j][1] = Bs[nb][k0 + t + 4];
            }
#pragma unroll
            for (int i = 0; i < 4; i++)
#pragma unroll
                for (int j = 0; j < 4; j++)
                    mma8(acc[i][j][0], acc[i][j][1], acc[i][j][2], acc[i][j][3],
                         af[i][0], af[i][1], af[i][2], af[i][3],
                         bf[j][0], bf[j][1]);
        }
        __syncthreads();
    }

#pragma unroll
    for (int j = 0; j < 4; j++) {
        int col = n0 + 8 * j + 2 * t;
        float bv0 = HAS_BIAS ? bias[col]     : 0.f;
        float bv1 = HAS_BIAS ? bias[col + 1] : 0.f;
#pragma unroll
        for (int i = 0; i < 4; i++) {
            long r0 = row0 + m0 + 16 * i + g;
            long r1 = r0 + 8;
            float v00 = acc[i][j][0] + bv0, v01 = acc[i][j][1] + bv1;
            float v10 = acc[i][j][2] + bv0, v11 = acc[i][j][3] + bv1;
            if (RELU) { v00 = fmaxf(v00, 0.f); v01 = fmaxf(v01, 0.f);
                        v10 = fmaxf(v10, 0.f); v11 = fmaxf(v11, 0.f); }
            if (RES) {
                float2 e0 = *(const float2*)&res[r0 * 128 + col];
                float2 e1 = *(const float2*)&res[r1 * 128 + col];
                v00 += e0.x; v01 += e0.y; v10 += e1.x; v11 += e1.y;
            }
            *(float2*)&Y[r0 * 128 + col] = make_float2(v00, v01);
            *(float2*)&Y[r1 * 128 + col] = make_float2(v10, v11);
        }
    }
}

// ---------------------------------------------------------------------------
// Xout[b,m,p] = relu( sum_n G0[b,m,n] * Yin[b,n,p] ),  128-row tile, K=256.
// Bs holds Yin transposed to [n(p)][k] so frag reads match the dense kernel.
// ---------------------------------------------------------------------------
__global__ __launch_bounds__(256)
void bmm_relu_tc(const float* __restrict__ G, const float* __restrict__ Yin,
                 float* __restrict__ Xout)
{
    __shared__ uint32_t As[128][PAD];
    __shared__ uint32_t Bs[128][PAD];

    const int tid  = threadIdx.x;
    const int lane = tid & 31, wid = tid >> 5;
    const int g = lane >> 2, t = lane & 3;
    const int m0 = (wid >> 2) * 64;
    const int n0 = (wid & 3) * 32;
    const int b = blockIdx.y;
    const int row0 = blockIdx.x * 128;
    const float* A  = G   + (long)b * M_ * M_;
    const float* Bm = Yin + (long)b * M_ * 128;

    float acc[4][4][4];
#pragma unroll
    for (int i = 0; i < 4; i++)
#pragma unroll
        for (int j = 0; j < 4; j++)
#pragma unroll
            for (int q = 0; q < 4; q++) acc[i][j][q] = 0.f;

    for (int kc = 0; kc < 256; kc += 32) {
#pragma unroll
        for (int it = 0; it < 4; it++) {
            int v = tid + it * 256;
            int r = v >> 3, c = (v & 7) * 4;
            float4 a4 = *(const float4*)&A[(row0 + r) * 256 + kc + c];
            As[r][c+0] = f2tf(a4.x); As[r][c+1] = f2tf(a4.y);
            As[r][c+2] = f2tf(a4.z); As[r][c+3] = f2tf(a4.w);
        }
        // transpose-fill: Bs[n][k] = Yin[kc+k][n]
#pragma unroll
        for (int it = 0; it < 16; it++) {
            int v = tid + it * 256;
            int k = v >> 7, n = v & 127;
            Bs[n][k] = f2tf(Bm[(kc + k) * 128 + n]);
        }
        __syncthreads();

#pragma unroll
        for (int ks = 0; ks < 4; ks++) {
            const int k0 = ks * 8;
            uint32_t af[4][4];
#pragma unroll
            for (int i = 0; i < 4; i++) {
                int mr = m0 + 16 * i;
                af[i][0] = As[mr + g    ][k0 + t];
                af[i][1] = As[mr + g + 8][k0 + t];
                af[i][2] = As[mr + g    ][k0 + t + 4];
                af[i][3] = As[mr + g + 8][k0 + t + 4];
            }
            uint32_t bf[4][2];
#pragma unroll
            for (int j = 0; j < 4; j++) {
                int nb = n0 + 8 * j + g;
                bf[j][0] = Bs[nb][k0 + t];
                bf[j][1] = Bs[nb][k0 + t + 4];
            }
#pragma unroll
            for (int i = 0; i < 4; i++)
#pragma unroll
                for (int j = 0; j < 4; j++)
                    mma8(acc[i][j][0], acc[i][j][1], acc[i][j][2], acc[i][j][3],
                         af[i][0], af[i][1], af[i][2], af[i][3],
                         bf[j][0], bf[j][1]);
        }
        __syncthreads();
    }

    float* O = Xout + (long)b * M_ * 128;
#pragma unroll
    for (int j = 0; j < 4; j++) {
        int col = n0 + 8 * j + 2 * t;
#pragma unroll
        for (int i = 0; i < 4; i++) {
            int r0 = row0 + m0 + 16 * i + g;
            int r1 = r0 + 8;
            *(float2*)&O[r0 * 128 + col] =
                make_float2(fmaxf(acc[i][j][0], 0.f), fmaxf(acc[i][j][1], 0.f));
            *(float2*)&O[r1 * 128 + col] =
                make_float2(fmaxf(acc[i][j][2], 0.f), fmaxf(acc[i][j][3], 0.f));
        }
    }
}

// ---------------------------------------------------------------------------
// Fused head: out[r] = f2_b + sum_n f2_W[n]*relu(H[r,:]·f1_W[n,:] + f1_b[n])
// 8 chunks of 128 output cols; each chunk is a full 128x128x128 tf32 GEMM.
// ---------------------------------------------------------------------------
__global__ __launch_bounds__(256)
void f1f2_fused_tc(const float* __restrict__ H, const float* __restrict__ W1,
                   const float* __restrict__ b1, const float* __restrict__ W2,
                   const float* __restrict__ b2, float* __restrict__ out)
{
    __shared__ uint32_t As[128][PAD];
    __shared__ uint32_t Bs[128][PAD];
    __shared__ float red[128][17];

    const int tid  = threadIdx.x;
    const int lane = tid & 31, wid = tid >> 5;
    const int g = lane >> 2, t = lane & 3;
    const int m0 = (wid >> 2) * 64;
    const int n0 = (wid & 3) * 32;
    const long row0 = (long)blockIdx.x * 128;

    float psum[8];
#pragma unroll
    for (int q = 0; q < 8; q++) psum[q] = 0.f;

    for (int nc = 0; nc < 1024; nc += 128) {
        float acc[4][4][4];
#pragma unroll
        for (int i = 0; i < 4; i++)
#pragma unroll
            for (int j = 0; j < 4; j++)
#pragma unroll
                for (int q = 0; q < 4; q++) acc[i][j][q] = 0.f;

        for (int kc = 0; kc < 128; kc += 32) {
#pragma unroll
            for (int it = 0; it < 4; it++) {
                int v = tid + it * 256;
                int r = v >> 3, c = (v & 7) * 4;
                float4 x4 = *(const float4*)&H[(row0 + r) * 128 + kc + c];
                As[r][c+0] = f2tf(x4.x); As[r][c+1] = f2tf(x4.y);
                As[r][c+2] = f2tf(x4.z); As[r][c+3] = f2tf(x4.w);
                float4 w4 = *(const float4*)&W1[(long)(nc + r) * 128 + kc + c];
                Bs[r][c+0] = f2tf(w4.x); Bs[r][c+1] = f2tf(w4.y);
                Bs[r][c+2] = f2tf(w4.z); Bs[r][c+3] = f2tf(w4.w);
            }
            __syncthreads();

#pragma unroll
            for (int ks = 0; ks < 4; ks++) {
                const int k0 = ks * 8;
                uint32_t af[4][4];
#pragma unroll
                for (int i = 0; i < 4; i++) {
                    int mr = m0 + 16 * i;
                    af[i][0] = As[mr + g    ][k0 + t];
                    af[i][1] = As[mr + g + 8][k0 + t];
                    af[i][2] = As[mr + g    ][k0 + t + 4];
                    af[i][3] = As[mr + g + 8][k0 + t + 4];
                }
                uint32_t bf[4][2];
#pragma unroll
                for (int j = 0; j < 4; j++) {
                    int nb = n0 + 8 * j + g;
                    bf[j][0] = Bs[nb][k0 + t];
                    bf[j][1] = Bs[nb][k0 + t + 4];
                }
#pragma unroll
                for (int i = 0; i < 4; i++)
#pragma unroll
                    for (int j = 0; j < 4; j++)
                        mma8(acc[i][j][0], acc[i][j][1], acc[i][j][2], acc[i][j][3],
                             af[i][0], af[i][1], af[i][2], af[i][3],
                             bf[j][0], bf[j][1]);
            }
            __syncthreads();
        }

#pragma unroll
        for (int j = 0; j < 4; j++) {
            int col = nc + n0 + 8 * j + 2 * t;
            float bb0 = b1[col], bb1 = b1[col + 1];
            float s0  = W2[col], s1  = W2[col + 1];
#pragma unroll
            for (int i = 0; i < 4; i++) {
                psum[2*i]   += fmaxf(acc[i][j][0] + bb0, 0.f) * s0
                             + fmaxf(acc[i][j][1] + bb1, 0.f) * s1;
                psum[2*i+1] += fmaxf(acc[i][j][2] + bb0, 0.f) * s0
                             + fmaxf(acc[i][j][3] + bb1, 0.f) * s1;
            }
        }
    }

    // reduce 16 partials per row (4 warp_n x 4 t)
    const int q = (wid & 3) * 4 + t;
#pragma unroll
    for (int i = 0; i < 4; i++) {
        red[m0 + 16 * i + g    ][q] = psum[2*i];
        red[m0 + 16 * i + g + 8][q] = psum[2*i+1];
    }
    __syncthreads();
    if (tid < 128) {
        float s = b2[0];
#pragma unroll
        for (int k = 0; k < 16; k++) s += red[tid][k];
        out[row0 + tid] = s;
    }
}

// ---------------------------------------------------------------------------
extern "C" void kernel_launch(void* const* d_in, const int* in_sizes, int n_in,
                              void* d_out, int out_size)
{
    const float* G     = (const float*)d_in[0];
    const float* xG    = (const float*)d_in[1];
    const float* gmlW  = (const float*)d_in[2];
    const float* gmlB  = (const float*)d_in[3];
    const float* lin0W = (const float*)d_in[4];
    const float* lin0B = (const float*)d_in[5];
    const float* rinW  = (const float*)d_in[6];
    const float* rinB  = (const float*)d_in[7];
    const float* rb1W  = (const float*)d_in[8];
    const float* rb1B  = (const float*)d_in[9];
    const float* rb2W  = (const float*)d_in[10];
    const float* routW = (const float*)d_in[11];
    const float* routB = (const float*)d_in[12];
    const float* f1W   = (const float*)d_in[13];
    const float* f1B   = (const float*)d_in[14];
    const float* f2W   = (const float*)d_in[15];
    const float* f2B   = (const float*)d_in[16];
    float* out = (float*)d_out;

    float *bY, *bX, *bH;
    cudaGetSymbolAddress((void**)&bY, g_Y);
    cudaGetSymbolAddress((void**)&bX, g_X);
    cudaGetSymbolAddress((void**)&bH, g_H);

    const int GB = BM_ / 128;   // 1024 blocks
    dim3 blk(256);

    // GNN message-passing layers
    const float* xcur = xG;
    for (int l = 0; l < NGL; l++) {
        gemm128_tc<true, false, false><<<GB, blk>>>(xcur, gmlW + (long)l * 128 * 128,
                                                    gmlB + l * 128, nullptr, bY);
        bmm_relu_tc<<<dim3(2, B_), blk>>>(G, bY, bX);
        xcur = bX;
    }

    // MLP trunk
    gemm128_tc<true, false, false><<<GB, blk>>>(bX, lin0W, lin0B, nullptr, bH);
    gemm128_tc<true, false, false><<<GB, blk>>>(bH, rinW, rinB, nullptr, bX);
    for (int i = 0; i < NRB; i++) {
        gemm128_tc<true, true,  false><<<GB, blk>>>(bX, rb1W + (long)i * 128 * 128,
                                                    rb1B + i * 128, nullptr, bY);
        gemm128_tc<false, false, true><<<GB, blk>>>(bY, rb2W + (long)i * 128 * 128,
                                                    nullptr, bX, bX);
    }
    gemm128_tc<true, false, false><<<GB, blk>>>(bX, routW, routB, nullptr, bH);

    // Fused f1 (relu) + f2 head
    f1f2_fused_tc<<<GB, blk>>>(bH, f1W, f1B, f2W, f2B, out);
}

// round 6
// speedup vs baseline: 3.2460x; 1.3652x over previous
#include <cuda_runtime.h>
#include <cstdint>

#define B_   512
#define M_   256
#define BM_  (B_*M_)      // 131072 rows
#define NGL  4
#define NRB  3

// Scratch (allocation-free rule: __device__ globals)
__device__ float g_Y[BM_*128];
__device__ float g_X[BM_*128];
__device__ float g_H[BM_*128];

// ---------------------------------------------------------------------------
// helpers
// ---------------------------------------------------------------------------
__device__ __forceinline__ uint32_t f2tf(float x) {
    uint32_t r;
    asm("cvt.rna.tf32.f32 %0, %1;" : "=r"(r) : "f"(x));
    return r;
}

__device__ __forceinline__ void mma8(float& c0, float& c1, float& c2, float& c3,
                                     uint32_t a0, uint32_t a1, uint32_t a2, uint32_t a3,
                                     uint32_t b0, uint32_t b1)
{
    asm volatile(
        "mma.sync.aligned.m16n8k8.row.col.f32.tf32.tf32.f32 "
        "{%0,%1,%2,%3}, {%4,%5,%6,%7}, {%8,%9}, {%0,%1,%2,%3};"
        : "+f"(c0), "+f"(c1), "+f"(c2), "+f"(c3)
        : "r"(a0), "r"(a1), "r"(a2), "r"(a3), "r"(b0), "r"(b1));
}

__device__ __forceinline__ uint32_t sptr(const void* p) {
    return (uint32_t)__cvta_generic_to_shared(p);
}
__device__ __forceinline__ void cp16(uint32_t s, const void* g) {
    asm volatile("cp.async.cg.shared.global [%0], [%1], 16;" :: "r"(s), "l"(g));
}
__device__ __forceinline__ void cp_commit() {
    asm volatile("cp.async.commit_group;");
}
template<int N> __device__ __forceinline__ void cp_wait() {
    asm volatile("cp.async.wait_group %0;" :: "n"(N));
}

// A tile: [128][ASTR] floats (row = m or n, col = k). ASTR=36 => frag reads
// hit 32 distinct banks (bank = (4g+t)%32).
#define ASTR 36
// bmm B tile: [32][BSTR] floats (row = k, col = n). BSTR=136 => bank = (8t+g)%32.
#define BSTR 136

// stage sizes in floats
#define STG_GEMM (128*ASTR*2)            // A + B, 9216 floats
#define STG_BMM  (128*ASTR + 32*BSTR)    // 8960 floats
#define DSMEM_GEMM (STG_GEMM*2*4)        // 73728 B
#define DSMEM_BMM  (STG_BMM*2*4)         // 71680 B

// ---------------------------------------------------------------------------
// warp-tile compute: 64x32 per warp, from A tile [128][ASTR] (k-minor) and
// B tile either n-major [n][k] stride ASTR (BKM=false) or k-major [k][n]
// stride BSTR (BKM=true). Accumulates 4 k-chunks of 8.
// ---------------------------------------------------------------------------
template<bool BKM>
__device__ __forceinline__ void compute_chunk(const float* __restrict__ A_s,
                                              const float* __restrict__ B_s,
                                              int m0, int n0, int g, int t,
                                              float acc[4][4][4])
{
#pragma unroll
    for (int ks = 0; ks < 4; ks++) {
        const int k0 = ks * 8;
        uint32_t af[4][4];
#pragma unroll
        for (int i = 0; i < 4; i++) {
            int mr = m0 + 16 * i;
            af[i][0] = f2tf(A_s[(mr + g    ) * ASTR + k0 + t]);
            af[i][1] = f2tf(A_s[(mr + g + 8) * ASTR + k0 + t]);
            af[i][2] = f2tf(A_s[(mr + g    ) * ASTR + k0 + t + 4]);
            af[i][3] = f2tf(A_s[(mr + g + 8) * ASTR + k0 + t + 4]);
        }
        uint32_t bf[4][2];
#pragma unroll
        for (int j = 0; j < 4; j++) {
            int nb = n0 + 8 * j + g;
            if (BKM) {
                bf[j][0] = f2tf(B_s[(k0 + t    ) * BSTR + nb]);
                bf[j][1] = f2tf(B_s[(k0 + t + 4) * BSTR + nb]);
            } else {
                bf[j][0] = f2tf(B_s[nb * ASTR + k0 + t]);
                bf[j][1] = f2tf(B_s[nb * ASTR + k0 + t + 4]);
            }
        }
#pragma unroll
        for (int i = 0; i < 4; i++)
#pragma unroll
            for (int j = 0; j < 4; j++)
                mma8(acc[i][j][0], acc[i][j][1], acc[i][j][2], acc[i][j][3],
                     af[i][0], af[i][1], af[i][2], af[i][3],
                     bf[j][0], bf[j][1]);
    }
}

// ---------------------------------------------------------------------------
// Y[r,n] = op( sum_k X[r,k]*W[n,k] (+bias[n]) ) (+ res[r,n]);  K=N=128.
// cp.async double-buffered, 4 k-chunks of 32.
// ---------------------------------------------------------------------------
template<bool HAS_BIAS, bool RELU, bool RES>
__global__ __launch_bounds__(256, 2)
void gemm128_tc(const float* __restrict__ X, const float* __restrict__ W,
                const float* __restrict__ bias, const float* __restrict__ res,
                float* __restrict__ Y)
{
    extern __shared__ float sm[];
    const int tid  = threadIdx.x;
    const int lane = tid & 31, wid = tid >> 5;
    const int g = lane >> 2, t = lane & 3;
    const int m0 = (wid >> 2) * 64;
    const int n0 = (wid & 3) * 32;
    const long row0 = (long)blockIdx.x * 128;

    auto fill = [&](int stage, int kc) {
        float* A_s = sm + stage * STG_GEMM;
        float* B_s = A_s + 128 * ASTR;
#pragma unroll
        for (int it = 0; it < 4; it++) {
            int v = tid + it * 256;
            int rr = v >> 3, cc = (v & 7) * 4;
            cp16(sptr(&A_s[rr * ASTR + cc]), &X[(row0 + rr) * 128 + kc + cc]);
            cp16(sptr(&B_s[rr * ASTR + cc]), &W[rr * 128 + kc + cc]);
        }
    };

    float acc[4][4][4];
#pragma unroll
    for (int i = 0; i < 4; i++)
#pragma unroll
        for (int j = 0; j < 4; j++)
#pragma unroll
            for (int q = 0; q < 4; q++) acc[i][j][q] = 0.f;

    fill(0, 0); cp_commit();
#pragma unroll
    for (int c = 0; c < 4; c++) {
        if (c + 1 < 4) { fill((c + 1) & 1, (c + 1) * 32); cp_commit(); cp_wait<1>(); }
        else           { cp_wait<0>(); }
        __syncthreads();
        const float* A_s = sm + (c & 1) * STG_GEMM;
        compute_chunk<false>(A_s, A_s + 128 * ASTR, m0, n0, g, t, acc);
        __syncthreads();
    }

#pragma unroll
    for (int j = 0; j < 4; j++) {
        int col = n0 + 8 * j + 2 * t;
        float bv0 = HAS_BIAS ? bias[col]     : 0.f;
        float bv1 = HAS_BIAS ? bias[col + 1] : 0.f;
#pragma unroll
        for (int i = 0; i < 4; i++) {
            long r0 = row0 + m0 + 16 * i + g;
            long r1 = r0 + 8;
            float v00 = acc[i][j][0] + bv0, v01 = acc[i][j][1] + bv1;
            float v10 = acc[i][j][2] + bv0, v11 = acc[i][j][3] + bv1;
            if (RELU) { v00 = fmaxf(v00, 0.f); v01 = fmaxf(v01, 0.f);
                        v10 = fmaxf(v10, 0.f); v11 = fmaxf(v11, 0.f); }
            if (RES) {
                float2 e0 = *(const float2*)&res[r0 * 128 + col];
                float2 e1 = *(const float2*)&res[r1 * 128 + col];
                v00 += e0.x; v01 += e0.y; v10 += e1.x; v11 += e1.y;
            }
            *(float2*)&Y[r0 * 128 + col] = make_float2(v00, v01);
            *(float2*)&Y[r1 * 128 + col] = make_float2(v10, v11);
        }
    }
}

// ---------------------------------------------------------------------------
// Xout[b,m,p] = relu( sum_n G0[b,m,n] * Yin[b,n,p] );  K=256, 8 k-chunks.
// B tile stored k-major (cp.async, no transpose).
// ---------------------------------------------------------------------------
__global__ __launch_bounds__(256, 2)
void bmm_relu_tc(const float* __restrict__ G, const float* __restrict__ Yin,
                 float* __restrict__ Xout)
{
    extern __shared__ float sm[];
    const int tid  = threadIdx.x;
    const int lane = tid & 31, wid = tid >> 5;
    const int g = lane >> 2, t = lane & 3;
    const int m0 = (wid >> 2) * 64;
    const int n0 = (wid & 3) * 32;
    const int b = blockIdx.y;
    const int row0 = blockIdx.x * 128;
    const float* A  = G   + (long)b * M_ * M_;
    const float* Bm = Yin + (long)b * M_ * 128;

    auto fill = [&](int stage, int kc) {
        float* A_s = sm + stage * STG_BMM;
        float* B_s = A_s + 128 * ASTR;
#pragma unroll
        for (int it = 0; it < 4; it++) {
            int v = tid + it * 256;
            int rr = v >> 3, cc = (v & 7) * 4;
            cp16(sptr(&A_s[rr * ASTR + cc]), &A[(row0 + rr) * 256 + kc + cc]);
            int kk = v >> 5, nn = (v & 31) * 4;
            cp16(sptr(&B_s[kk * BSTR + nn]), &Bm[(kc + kk) * 128 + nn]);
        }
    };

    float acc[4][4][4];
#pragma unroll
    for (int i = 0; i < 4; i++)
#pragma unroll
        for (int j = 0; j < 4; j++)
#pragma unroll
            for (int q = 0; q < 4; q++) acc[i][j][q] = 0.f;

    fill(0, 0); cp_commit();
    for (int c = 0; c < 8; c++) {
        if (c + 1 < 8) { fill((c + 1) & 1, (c + 1) * 32); cp_commit(); cp_wait<1>(); }
        else           { cp_wait<0>(); }
        __syncthreads();
        const float* A_s = sm + (c & 1) * STG_BMM;
        compute_chunk<true>(A_s, A_s + 128 * ASTR, m0, n0, g, t, acc);
        __syncthreads();
    }

    float* O = Xout + (long)b * M_ * 128;
#pragma unroll
    for (int j = 0; j < 4; j++) {
        int col = n0 + 8 * j + 2 * t;
#pragma unroll
        for (int i = 0; i < 4; i++) {
            int r0 = row0 + m0 + 16 * i + g;
            int r1 = r0 + 8;
            *(float2*)&O[r0 * 128 + col] =
                make_float2(fmaxf(acc[i][j][0], 0.f), fmaxf(acc[i][j][1], 0.f));
            *(float2*)&O[r1 * 128 + col] =
                make_float2(fmaxf(acc[i][j][2], 0.f), fmaxf(acc[i][j][3], 0.f));
        }
    }
}

// ---------------------------------------------------------------------------
// Fused head: out[r] = f2_b + sum_n f2_W[n]*relu(H[r,:]·f1_W[n,:] + f1_b[n])
// 8 n-chunks x 4 k-chunks, single cp.async pipeline across all 32 chunks.
// ---------------------------------------------------------------------------
__global__ __launch_bounds__(256, 2)
void f1f2_fused_tc(const float* __restrict__ H, const float* __restrict__ W1,
                   const float* __restrict__ b1, const float* __restrict__ W2,
                   const float* __restrict__ b2, float* __restrict__ out)
{
    extern __shared__ float sm[];
    const int tid  = threadIdx.x;
    const int lane = tid & 31, wid = tid >> 5;
    const int g = lane >> 2, t = lane & 3;
    const int m0 = (wid >> 2) * 64;
    const int n0 = (wid & 3) * 32;
    const long row0 = (long)blockIdx.x * 128;

    auto fill = [&](int stage, int q) {
        float* A_s = sm + stage * STG_GEMM;
        float* B_s = A_s + 128 * ASTR;
        int nc = (q >> 2) * 128;
        int kc = (q & 3) * 32;
#pragma unroll
        for (int it = 0; it < 4; it++) {
            int v = tid + it * 256;
            int rr = v >> 3, cc = (v & 7) * 4;
            cp16(sptr(&A_s[rr * ASTR + cc]), &H[(row0 + rr) * 128 + kc + cc]);
            cp16(sptr(&B_s[rr * ASTR + cc]), &W1[(long)(nc + rr) * 128 + kc + cc]);
        }
    };

    float psum[8];
#pragma unroll
    for (int q = 0; q < 8; q++) psum[q] = 0.f;

    fill(0, 0); cp_commit();
    for (int nci = 0; nci < 8; nci++) {
        float acc[4][4][4];
#pragma unroll
        for (int i = 0; i < 4; i++)
#pragma unroll
            for (int j = 0; j < 4; j++)
#pragma unroll
                for (int q = 0; q < 4; q++) acc[i][j][q] = 0.f;

#pragma unroll
        for (int kci = 0; kci < 4; kci++) {
            int q = nci * 4 + kci;
            if (q + 1 < 32) { fill((q + 1) & 1, q + 1); cp_commit(); cp_wait<1>(); }
            else            { cp_wait<0>(); }
            __syncthreads();
            const float* A_s = sm + (q & 1) * STG_GEMM;
            compute_chunk<false>(A_s, A_s + 128 * ASTR, m0, n0, g, t, acc);
            __syncthreads();
        }

        int ncb = nci * 128;
#pragma unroll
        for (int j = 0; j < 4; j++) {
            int col = ncb + n0 + 8 * j + 2 * t;
            float bb0 = b1[col], bb1 = b1[col + 1];
            float s0  = W2[col], s1  = W2[col + 1];
#pragma unroll
            for (int i = 0; i < 4; i++) {
                psum[2*i]   += fmaxf(acc[i][j][0] + bb0, 0.f) * s0
                             + fmaxf(acc[i][j][1] + bb1, 0.f) * s1;
                psum[2*i+1] += fmaxf(acc[i][j][2] + bb0, 0.f) * s0
                             + fmaxf(acc[i][j][3] + bb1, 0.f) * s1;
            }
        }
    }

    // reduce 16 partials per row (4 warp_n x 4 t); reuse smem (all compute done)
    float (*red)[17] = (float(*)[17])sm;
    const int qn = (wid & 3) * 4 + t;
#pragma unroll
    for (int i = 0; i < 4; i++) {
        red[m0 + 16 * i + g    ][qn] = psum[2*i];
        red[m0 + 16 * i + g + 8][qn] = psum[2*i+1];
    }
    __syncthreads();
    if (tid < 128) {
        float s = b2[0];
#pragma unroll
        for (int k = 0; k < 16; k++) s += red[tid][k];
        out[row0 + tid] = s;
    }
}

// ---------------------------------------------------------------------------
extern "C" void kernel_launch(void* const* d_in, const int* in_sizes, int n_in,
                              void* d_out, int out_size)
{
    const float* G     = (const float*)d_in[0];
    const float* xG    = (const float*)d_in[1];
    const float* gmlW  = (const float*)d_in[2];
    const float* gmlB  = (const float*)d_in[3];
    const float* lin0W = (const float*)d_in[4];
    const float* lin0B = (const float*)d_in[5];
    const float* rinW  = (const float*)d_in[6];
    const float* rinB  = (const float*)d_in[7];
    const float* rb1W  = (const float*)d_in[8];
    const float* rb1B  = (const float*)d_in[9];
    const float* rb2W  = (const float*)d_in[10];
    const float* routW = (const float*)d_in[11];
    const float* routB = (const float*)d_in[12];
    const float* f1W   = (const float*)d_in[13];
    const float* f1B   = (const float*)d_in[14];
    const float* f2W   = (const float*)d_in[15];
    const float* f2B   = (const float*)d_in[16];
    float* out = (float*)d_out;

    float *bY, *bX, *bH;
    cudaGetSymbolAddress((void**)&bY, g_Y);
    cudaGetSymbolAddress((void**)&bX, g_X);
    cudaGetSymbolAddress((void**)&bH, g_H);

    // raise dynamic-smem caps (idempotent; executes immediately, not captured)
    cudaFuncSetAttribute(gemm128_tc<true, false, false>,
                         cudaFuncAttributeMaxDynamicSharedMemorySize, DSMEM_GEMM);
    cudaFuncSetAttribute(gemm128_tc<true, true, false>,
                         cudaFuncAttributeMaxDynamicSharedMemorySize, DSMEM_GEMM);
    cudaFuncSetAttribute(gemm128_tc<false, false, true>,
                         cudaFuncAttributeMaxDynamicSharedMemorySize, DSMEM_GEMM);
    cudaFuncSetAttribute(bmm_relu_tc,
                         cudaFuncAttributeMaxDynamicSharedMemorySize, DSMEM_BMM);
    cudaFuncSetAttribute(f1f2_fused_tc,
                         cudaFuncAttributeMaxDynamicSharedMemorySize, DSMEM_GEMM);

    const int GB = BM_ / 128;   // 1024 blocks
    dim3 blk(256);

    // GNN message-passing layers
    const float* xcur = xG;
    for (int l = 0; l < NGL; l++) {
        gemm128_tc<true, false, false><<<GB, blk, DSMEM_GEMM>>>(
            xcur, gmlW + (long)l * 128 * 128, gmlB + l * 128, nullptr, bY);
        bmm_relu_tc<<<dim3(2, B_), blk, DSMEM_BMM>>>(G, bY, bX);
        xcur = bX;
    }

    // MLP trunk
    gemm128_tc<true, false, false><<<GB, blk, DSMEM_GEMM>>>(bX, lin0W, lin0B, nullptr, bH);
    gemm128_tc<true, false, false><<<GB, blk, DSMEM_GEMM>>>(bH, rinW, rinB, nullptr, bX);
    for (int i = 0; i < NRB; i++) {
        gemm128_tc<true, true,  false><<<GB, blk, DSMEM_GEMM>>>(
            bX, rb1W + (long)i * 128 * 128, rb1B + i * 128, nullptr, bY);
        gemm128_tc<false, false, true><<<GB, blk, DSMEM_GEMM>>>(
            bY, rb2W + (long)i * 128 * 128, nullptr, bX, bX);
    }
    gemm128_tc<true, false, false><<<GB, blk, DSMEM_GEMM>>>(bX, routW, routB, nullptr, bH);

    // Fused f1 (relu) + f2 head
    f1f2_fused_tc<<<GB, blk, DSMEM_GEMM>>>(bH, f1W, f1B, f2W, f2B, out);
}

// round 8
// speedup vs baseline: 3.3062x; 1.0186x over previous
#include <cuda_runtime.h>
#include <cstdint>

#define B_   512
#define M_   256
#define BM_  (B_*M_)      // 131072 rows
#define NGL  4

// Scratch (allocation-free rule: __device__ globals)
__device__ float g_Y[BM_*128];
__device__ float g_X[BM_*128];

// ---------------------------------------------------------------------------
// helpers
// ---------------------------------------------------------------------------
__device__ __forceinline__ uint32_t f2tf(float x) {
    uint32_t r;
    asm("cvt.rna.tf32.f32 %0, %1;" : "=r"(r) : "f"(x));
    return r;
}

__device__ __forceinline__ void mma8(float& c0, float& c1, float& c2, float& c3,
                                     uint32_t a0, uint32_t a1, uint32_t a2, uint32_t a3,
                                     uint32_t b0, uint32_t b1)
{
    asm volatile(
        "mma.sync.aligned.m16n8k8.row.col.f32.tf32.tf32.f32 "
        "{%0,%1,%2,%3}, {%4,%5,%6,%7}, {%8,%9}, {%0,%1,%2,%3};"
        : "+f"(c0), "+f"(c1), "+f"(c2), "+f"(c3)
        : "r"(a0), "r"(a1), "r"(a2), "r"(a3), "r"(b0), "r"(b1));
}

__device__ __forceinline__ uint32_t sptr(const void* p) {
    return (uint32_t)__cvta_generic_to_shared(p);
}
__device__ __forceinline__ void cp16(uint32_t s, const void* g) {
    asm volatile("cp.async.cg.shared.global [%0], [%1], 16;" :: "r"(s), "l"(g));
}
__device__ __forceinline__ void cp_commit() {
    asm volatile("cp.async.commit_group;");
}
template<int N> __device__ __forceinline__ void cp_wait() {
    asm volatile("cp.async.wait_group %0;" :: "n"(N));
}

// Chunk tiles: [128][ASTR] floats (row = m or n, col = k-within-chunk).
// ASTR=36 => frag reads hit 32 distinct banks (bank = (4g+t)%32).
#define ASTR 36
// bmm B tile: [32][BSTR] floats (row = k, col = n). BSTR=136 => bank=(8t+g)%32.
#define BSTR 136

#define TILE_F   (128*ASTR)              // 4608 floats per 128x32 chunk tile
#define STG_GEMM (TILE_F*2)              // A + B chunk
#define STG_BMM  (TILE_F + 32*BSTR)      // 8960 floats
#define DSMEM_GEMM  (STG_GEMM*2*4)       // 73728 B (2-stage)
#define DSMEM_BMM3  (STG_BMM*3*4)        // 107520 B (3-stage)

// trunk smem: H0,H1 swizzled full tiles (128*128) + 2 weight chunk buffers
#define HTILE_F  (128*128)
#define WCHK_F   TILE_F
#define DSMEM_TRUNK ((2*HTILE_F + 2*WCHK_F)*4)   // 167936 B

// swizzled H addressing: phys col = k ^ ((r&7)<<2); 4-float groups preserved
__device__ __forceinline__ int hsw(int r, int k) {
    return r * 128 + (k ^ ((r & 7) << 2));
}

// ---------------------------------------------------------------------------
// warp-tile compute over one 32-k chunk from padded chunk tiles.
// A n-major [.][ASTR]; B n-major stride ASTR (BKM=false) or k-major stride
// BSTR (BKM=true).
// ---------------------------------------------------------------------------
template<bool BKM>
__device__ __forceinline__ void compute_chunk(const float* __restrict__ A_s,
                                              const float* __restrict__ B_s,
                                              int m0, int n0, int g, int t,
                                              float acc[4][4][4])
{
#pragma unroll
    for (int ks = 0; ks < 4; ks++) {
        const int k0 = ks * 8;
        uint32_t af[4][4];
#pragma unroll
        for (int i = 0; i < 4; i++) {
            int mr = m0 + 16 * i;
            af[i][0] = f2tf(A_s[(mr + g    ) * ASTR + k0 + t]);
            af[i][1] = f2tf(A_s[(mr + g + 8) * ASTR + k0 + t]);
            af[i][2] = f2tf(A_s[(mr + g    ) * ASTR + k0 + t + 4]);
            af[i][3] = f2tf(A_s[(mr + g + 8) * ASTR + k0 + t + 4]);
        }
        uint32_t bf[4][2];
#pragma unroll
        for (int j = 0; j < 4; j++) {
            int nb = n0 + 8 * j + g;
            if (BKM) {
                bf[j][0] = f2tf(B_s[(k0 + t    ) * BSTR + nb]);
                bf[j][1] = f2tf(B_s[(k0 + t + 4) * BSTR + nb]);
            } else {
                bf[j][0] = f2tf(B_s[nb * ASTR + k0 + t]);
                bf[j][1] = f2tf(B_s[nb * ASTR + k0 + t + 4]);
            }
        }
#pragma unroll
        for (int i = 0; i < 4; i++)
#pragma unroll
            for (int j = 0; j < 4; j++)
                mma8(acc[i][j][0], acc[i][j][1], acc[i][j][2], acc[i][j][3],
                     af[i][0], af[i][1], af[i][2], af[i][3],
                     bf[j][0], bf[j][1]);
    }
}

// trunk variant: A from swizzled full H tile (global k = kc+...), W from
// padded chunk buffer (k within chunk).
__device__ __forceinline__ void compute_chunk_swz(const float* __restrict__ H_s,
                                                  const float* __restrict__ W_s,
                                                  int kc, int m0, int n0,
                                                  int g, int t,
                                                  float acc[4][4][4])
{
    const int sw = g << 2;
#pragma unroll
    for (int ks = 0; ks < 4; ks++) {
        const int k0 = ks * 8;
        uint32_t af[4][4];
#pragma unroll
        for (int i = 0; i < 4; i++) {
            int r0 = m0 + 16 * i + g;      // r&7 == g
            int r1 = r0 + 8;               // r&7 == g
            af[i][0] = f2tf(H_s[r0 * 128 + ((kc + k0 + t    ) ^ sw)]);
            af[i][1] = f2tf(H_s[r1 * 128 + ((kc + k0 + t    ) ^ sw)]);
            af[i][2] = f2tf(H_s[r0 * 128 + ((kc + k0 + t + 4) ^ sw)]);
            af[i][3] = f2tf(H_s[r1 * 128 + ((kc + k0 + t + 4) ^ sw)]);
        }
        uint32_t bf[4][2];
#pragma unroll
        for (int j = 0; j < 4; j++) {
            int nb = n0 + 8 * j + g;
            bf[j][0] = f2tf(W_s[nb * ASTR + k0 + t]);
            bf[j][1] = f2tf(W_s[nb * ASTR + k0 + t + 4]);
        }
#pragma unroll
        for (int i = 0; i < 4; i++)
#pragma unroll
            for (int j = 0; j < 4; j++)
                mma8(acc[i][j][0], acc[i][j][1], acc[i][j][2], acc[i][j][3],
                     af[i][0], af[i][1], af[i][2], af[i][3],
                     bf[j][0], bf[j][1]);
    }
}

// ---------------------------------------------------------------------------
// gml layer GEMM: Y[r,n] = sum_k X[r,k]*W[n,k] + bias[n];  K=N=128.
// ---------------------------------------------------------------------------
__global__ __launch_bounds__(256, 2)
void gemm128_tc(const float* __restrict__ X, const float* __restrict__ W,
                const float* __restrict__ bias, float* __restrict__ Y)
{
    extern __shared__ float sm[];
    const int tid  = threadIdx.x;
    const int lane = tid & 31, wid = tid >> 5;
    const int g = lane >> 2, t = lane & 3;
    const int m0 = (wid >> 2) * 64;
    const int n0 = (wid & 3) * 32;
    const long row0 = (long)blockIdx.x * 128;

    auto fill = [&](int stage, int kc) {
        float* A_s = sm + stage * STG_GEMM;
        float* B_s = A_s + TILE_F;
#pragma unroll
        for (int it = 0; it < 4; it++) {
            int v = tid + it * 256;
            int rr = v >> 3, cc = (v & 7) * 4;
            cp16(sptr(&A_s[rr * ASTR + cc]), &X[(row0 + rr) * 128 + kc + cc]);
            cp16(sptr(&B_s[rr * ASTR + cc]), &W[rr * 128 + kc + cc]);
        }
    };

    float acc[4][4][4];
#pragma unroll
    for (int i = 0; i < 4; i++)
#pragma unroll
        for (int j = 0; j < 4; j++)
#pragma unroll
            for (int q = 0; q < 4; q++) acc[i][j][q] = 0.f;

    fill(0, 0); cp_commit();
#pragma unroll
    for (int c = 0; c < 4; c++) {
        if (c + 1 < 4) { fill((c + 1) & 1, (c + 1) * 32); cp_commit(); cp_wait<1>(); }
        else           { cp_wait<0>(); }
        __syncthreads();
        const float* A_s = sm + (c & 1) * STG_GEMM;
        compute_chunk<false>(A_s, A_s + TILE_F, m0, n0, g, t, acc);
        __syncthreads();
    }

#pragma unroll
    for (int j = 0; j < 4; j++) {
        int col = n0 + 8 * j + 2 * t;
        float bv0 = bias[col], bv1 = bias[col + 1];
#pragma unroll
        for (int i = 0; i < 4; i++) {
            long r0 = row0 + m0 + 16 * i + g;
            long r1 = r0 + 8;
            *(float2*)&Y[r0 * 128 + col] = make_float2(acc[i][j][0] + bv0,
                                                       acc[i][j][1] + bv1);
            *(float2*)&Y[r1 * 128 + col] = make_float2(acc[i][j][2] + bv0,
                                                       acc[i][j][3] + bv1);
        }
    }
}

// ---------------------------------------------------------------------------
// Xout[b,m,p] = relu( sum_n G0[b,m,n] * Yin[b,n,p] );  K=256, 8 k-chunks,
// 3-stage cp.async ring.
// ---------------------------------------------------------------------------
__global__ __launch_bounds__(256, 2)
void bmm_relu_tc(const float* __restrict__ G, const float* __restrict__ Yin,
                 float* __restrict__ Xout)
{
    extern __shared__ float sm[];
    const int tid  = threadIdx.x;
    const int lane = tid & 31, wid = tid >> 5;
    const int g = lane >> 2, t = lane & 3;
    const int m0 = (wid >> 2) * 64;
    const int n0 = (wid & 3) * 32;
    const int b = blockIdx.y;
    const int row0 = blockIdx.x * 128;
    const float* A  = G   + (long)b * M_ * M_;
    const float* Bm = Yin + (long)b * M_ * 128;

    auto fill = [&](int stage, int kc) {
        float* A_s = sm + stage * STG_BMM;
        float* B_s = A_s + TILE_F;
#pragma unroll
        for (int it = 0; it < 4; it++) {
            int v = tid + it * 256;
            int rr = v >> 3, cc = (v & 7) * 4;
            cp16(sptr(&A_s[rr * ASTR + cc]), &A[(row0 + rr) * 256 + kc + cc]);
            int kk = v >> 5, nn = (v & 31) * 4;
            cp16(sptr(&B_s[kk * BSTR + nn]), &Bm[(kc + kk) * 128 + nn]);
        }
    };

    float acc[4][4][4];
#pragma unroll
    for (int i = 0; i < 4; i++)
#pragma unroll
        for (int j = 0; j < 4; j++)
#pragma unroll
            for (int q = 0; q < 4; q++) acc[i][j][q] = 0.f;

    fill(0, 0); cp_commit();
    fill(1, 32); cp_commit();
    for (int c = 0; c < 8; c++) {
        if (c + 2 < 8) { fill((c + 2) % 3, (c + 2) * 32); cp_commit(); cp_wait<2>(); }
        else if (c + 1 < 8) cp_wait<1>();
        else                cp_wait<0>();
        __syncthreads();
        const float* A_s = sm + (c % 3) * STG_BMM;
        compute_chunk<true>(A_s, A_s + TILE_F, m0, n0, g, t, acc);
        __syncthreads();
    }

    float* O = Xout + (long)b * M_ * 128;
#pragma unroll
    for (int j = 0; j < 4; j++) {
        int col = n0 + 8 * j + 2 * t;
#pragma unroll
        for (int i = 0; i < 4; i++) {
            int r0 = row0 + m0 + 16 * i + g;
            int r1 = r0 + 8;
            *(float2*)&O[r0 * 128 + col] =
                make_float2(fmaxf(acc[i][j][0], 0.f), fmaxf(acc[i][j][1], 0.f));
            *(float2*)&O[r1 * 128 + col] =
                make_float2(fmaxf(acc[i][j][2], 0.f), fmaxf(acc[i][j][3], 0.f));
        }
    }
}

// ---------------------------------------------------------------------------
// Mega-fused trunk + head. One block = 128 rows. Activations live in two
// swizzled 128x128 smem tiles (H0/H1); weights streamed per 32-k chunk
// through a 2-buffer cp.async ring (chunk overlapped with its MMAs).
// Stages: 0 lin0, 1 rin, {2,4,6} rb1_i (bias+relu), {3,5,7} rb2_i (+res),
//         8 rout, 9..16 head n-chunks (f1 relu dot f2). 68 chunk-slots total.
// ---------------------------------------------------------------------------
#define NSTG 17
#define NSLOT (NSTG*4)

__global__ __launch_bounds__(256, 1)
void trunk_head_fused(const float* __restrict__ X,
    const float* __restrict__ lin0W, const float* __restrict__ lin0B,
    const float* __restrict__ rinW,  const float* __restrict__ rinB,
    const float* __restrict__ rb1W,  const float* __restrict__ rb1B,
    const float* __restrict__ rb2W,
    const float* __restrict__ routW, const float* __restrict__ routB,
    const float* __restrict__ f1W,   const float* __restrict__ f1B,
    const float* __restrict__ f2W,   const float* __restrict__ f2B,
    float* __restrict__ out)
{
    extern __shared__ float sm[];
    float* H0 = sm;                        // swizzled 128x128
    float* H1 = sm + HTILE_F;              // swizzled 128x128
    float* Wc = sm + 2 * HTILE_F;          // 2 x [128][ASTR] chunk buffers

    const int tid  = threadIdx.x;
    const int lane = tid & 31, wid = tid >> 5;
    const int g = lane >> 2, t = lane & 3;
    const int m0 = (wid >> 2) * 64;
    const int n0 = (wid & 3) * 32;
    const long row0 = (long)blockIdx.x * 128;

    // weight / bias stage tables
    const float* wp[NSTG];
    wp[0] = lin0W;  wp[1] = rinW;
    wp[2] = rb1W;            wp[3] = rb2W;
    wp[4] = rb1W + 16384;    wp[5] = rb2W + 16384;
    wp[6] = rb1W + 32768;    wp[7] = rb2W + 32768;
    wp[8] = routW;
#pragma unroll
    for (int i = 0; i < 8; i++) wp[9 + i] = f1W + (long)i * 16384;
    const float* bp[9] = { lin0B, rinB, rb1B, nullptr, rb1B + 128, nullptr,
                           rb1B + 256, nullptr, routB };

    // fill one 128x32 weight chunk (4096 floats, 4 cp16 per thread)
    auto fillWchunk = [&](int buf, int slot) {
        const float* Wp = wp[slot >> 2];
        int kc = (slot & 3) * 32;
        float* W_s = Wc + buf * WCHK_F;
#pragma unroll
        for (int it = 0; it < 4; it++) {
            int v = tid + it * 256;
            int rr = v >> 3, cc = (v & 7) * 4;
            cp16(sptr(&W_s[rr * ASTR + cc]), &Wp[rr * 128 + kc + cc]);
        }
    };

    // prologue: X -> H0 (swizzled), weight chunk 0 -> buf 0
#pragma unroll
    for (int it = 0; it < 16; it++) {
        int v = tid + it * 256;
        int rr = v >> 5, cc = (v & 31) * 4;
        cp16(sptr(&H0[rr * 128 + (cc ^ ((rr & 7) << 2))]),
             &X[(row0 + rr) * 128 + cc]);
    }
    fillWchunk(0, 0);
    cp_commit(); cp_wait<0>(); __syncthreads();

    float psum[8];
#pragma unroll
    for (int q = 0; q < 8; q++) psum[q] = 0.f;

    float acc[4][4][4];

    for (int q = 0; q < NSLOT; q++) {
        const int s = q >> 2, c = q & 3;

        if (q + 1 < NSLOT) { fillWchunk((q + 1) & 1, q + 1); cp_commit(); }

        if (c == 0) {
#pragma unroll
            for (int i = 0; i < 4; i++)
#pragma unroll
                for (int j = 0; j < 4; j++)
#pragma unroll
                    for (int z = 0; z < 4; z++) acc[i][j][z] = 0.f;
        }

        const float* A_s = ((s & 1) || s >= 9) ? H1 : H0;
        compute_chunk_swz(A_s, Wc + (q & 1) * WCHK_F, c * 32, m0, n0, g, t, acc);

        if (c == 3) {
            if (s < 9) {
                float* D = (s & 1) ? H0 : H1;
                const bool relu = (s == 2 || s == 4 || s == 6);
                const bool res  = (s == 3 || s == 5 || s == 7);
                const float* bias = bp[s];
                const int sw = g << 2;
#pragma unroll
                for (int j = 0; j < 4; j++) {
                    int col = n0 + 8 * j + 2 * t;
                    float bv0 = bias ? bias[col]     : 0.f;
                    float bv1 = bias ? bias[col + 1] : 0.f;
#pragma unroll
                    for (int i = 0; i < 4; i++) {
                        int r0 = m0 + 16 * i + g;     // r&7 == g
                        int r1 = r0 + 8;
                        int p0 = r0 * 128 + (col ^ sw);
                        int p1 = r1 * 128 + (col ^ sw);
                        float v00 = acc[i][j][0] + bv0, v01 = acc[i][j][1] + bv1;
                        float v10 = acc[i][j][2] + bv0, v11 = acc[i][j][3] + bv1;
                        if (relu) { v00 = fmaxf(v00, 0.f); v01 = fmaxf(v01, 0.f);
                                    v10 = fmaxf(v10, 0.f); v11 = fmaxf(v11, 0.f); }
                        if (res) {
                            float2 e0 = *(const float2*)&D[p0];
                            float2 e1 = *(const float2*)&D[p1];
                            v00 += e0.x; v01 += e0.y; v10 += e1.x; v11 += e1.y;
                        }
                        *(float2*)&D[p0] = make_float2(v00, v01);
                        *(float2*)&D[p1] = make_float2(v10, v11);
                    }
                }
            } else {
                int ncb = (s - 9) * 128;
#pragma unroll
                for (int j = 0; j < 4; j++) {
                    int col = ncb + n0 + 8 * j + 2 * t;
                    float bb0 = f1B[col], bb1 = f1B[col + 1];
                    float s0  = f2W[col], s1  = f2W[col + 1];
#pragma unroll
                    for (int i = 0; i < 4; i++) {
                        psum[2*i]   += fmaxf(acc[i][j][0] + bb0, 0.f) * s0
                                     + fmaxf(acc[i][j][1] + bb1, 0.f) * s1;
                        psum[2*i+1] += fmaxf(acc[i][j][2] + bb0, 0.f) * s0
                                     + fmaxf(acc[i][j][3] + bb1, 0.f) * s1;
                    }
                }
            }
        }

        if (q + 1 < NSLOT) cp_wait<0>();
        __syncthreads();
    }

    // reduce 16 partials per row; overlay scratch on weight buffers
    float (*red)[17] = (float(*)[17])Wc;
    const int qn = (wid & 3) * 4 + t;
#pragma unroll
    for (int i = 0; i < 4; i++) {
        red[m0 + 16 * i + g    ][qn] = psum[2*i];
        red[m0 + 16 * i + g + 8][qn] = psum[2*i+1];
    }
    __syncthreads();
    if (tid < 128) {
        float sum = f2B[0];
#pragma unroll
        for (int k = 0; k < 16; k++) sum += red[tid][k];
        out[row0 + tid] = sum;
    }
}

// ---------------------------------------------------------------------------
extern "C" void kernel_launch(void* const* d_in, const int* in_sizes, int n_in,
                              void* d_out, int out_size)
{
    const float* G     = (const float*)d_in[0];
    const float* xG    = (const float*)d_in[1];
    const float* gmlW  = (const float*)d_in[2];
    const float* gmlB  = (const float*)d_in[3];
    const float* lin0W = (const float*)d_in[4];
    const float* lin0B = (const float*)d_in[5];
    const float* rinW  = (const float*)d_in[6];
    const float* rinB  = (const float*)d_in[7];
    const float* rb1W  = (const float*)d_in[8];
    const float* rb1B  = (const float*)d_in[9];
    const float* rb2W  = (const float*)d_in[10];
    const float* routW = (const float*)d_in[11];
    const float* routB = (const float*)d_in[12];
    const float* f1W   = (const float*)d_in[13];
    const float* f1B   = (const float*)d_in[14];
    const float* f2W   = (const float*)d_in[15];
    const float* f2B   = (const float*)d_in[16];
    float* out = (float*)d_out;

    float *bY, *bX;
    cudaGetSymbolAddress((void**)&bY, g_Y);
    cudaGetSymbolAddress((void**)&bX, g_X);

    cudaFuncSetAttribute(gemm128_tc,
                         cudaFuncAttributeMaxDynamicSharedMemorySize, DSMEM_GEMM);
    cudaFuncSetAttribute(bmm_relu_tc,
                         cudaFuncAttributeMaxDynamicSharedMemorySize, DSMEM_BMM3);
    cudaFuncSetAttribute(trunk_head_fused,
                         cudaFuncAttributeMaxDynamicSharedMemorySize, DSMEM_TRUNK);

    const int GB = BM_ / 128;   // 1024 blocks
    dim3 blk(256);

    // GNN message-passing layers
    const float* xcur = xG;
    for (int l = 0; l < NGL; l++) {
        gemm128_tc<<<GB, blk, DSMEM_GEMM>>>(xcur, gmlW + (long)l * 16384,
                                            gmlB + l * 128, bY);
        bmm_relu_tc<<<dim3(2, B_), blk, DSMEM_BMM3>>>(G, bY, bX);
        xcur = bX;
    }

    // Fused MLP trunk + head (one kernel, activations never leave smem)
    trunk_head_fused<<<GB, blk, DSMEM_TRUNK>>>(bX,
        lin0W, lin0B, rinW, rinB, rb1W, rb1B, rb2W, routW, routB,
        f1W, f1B, f2W, f2B, out);
}